// round 6
// baseline (speedup 1.0000x reference)
#include <cuda_runtime.h>

#define VSZ 50257
#define Dk  50
#define TT  1024
#define BSZ 1024
#define BB  8
#define NT  672

// Precomputed emb @ kx1 + b1[0] table: [V, 96] fp32 (L2-resident, 19.3MB)
__device__ float g_proj1[VSZ * 96];

typedef unsigned long long u64;

__device__ __forceinline__ u64 pk2(float a, float b) {
    u64 r; asm("mov.b64 %0, {%1, %2};" : "=l"(r) : "f"(a), "f"(b)); return r;
}
__device__ __forceinline__ void upk2(u64 v, float& a, float& b) {
    asm("mov.b64 {%0, %1}, %2;" : "=f"(a), "=f"(b) : "l"(v));
}
__device__ __forceinline__ u64 ffma2(u64 a, u64 b, u64 c) {
    u64 d; asm("fma.rn.f32x2 %0, %1, %2, %3;" : "=l"(d) : "l"(a), "l"(b), "l"(c)); return d;
}
__device__ __forceinline__ float sgm(float x) { return 1.0f / (1.0f + __expf(-x)); }
__device__ __forceinline__ float tnh(float x) { return 2.0f * sgm(2.0f * x) - 1.0f; }

// scalar GRU update
__device__ __forceinline__ float gru1s(float xz, float hz, float xr, float hr,
                                       float xh, float hh, float hold) {
    float z = sgm(xz + hz);
    float r = sgm(xr + hr);
    float c = tnh(xh + r * hh);
    return z * hold + (1.0f - z) * c;
}

// ---------------------------------------------------------------------------
__global__ void proj_kernel(const float* __restrict__ emb,
                            const float* __restrict__ kx1,
                            const float* __restrict__ b1) {
    __shared__ float kxs[Dk * 96];
    __shared__ float embs[16 * Dk];
    int tid = threadIdx.x;
    for (int i = tid; i < Dk * 96; i += 256) kxs[i] = kx1[i];
    int vbase = blockIdx.x * 16;
    for (int i = tid; i < 16 * Dk; i += 256) {
        int r = i / Dk, d = i - r * Dk;
        int v = vbase + r;
        embs[i] = (v < VSZ) ? emb[v * Dk + d] : 0.0f;
    }
    __syncthreads();
    for (int i = tid; i < 16 * 96; i += 256) {
        int r = i / 96, j = i - r * 96;
        int v = vbase + r;
        if (v >= VSZ) continue;
        float acc = b1[j];
        #pragma unroll
        for (int d = 0; d < Dk; d++)
            acc = fmaf(embs[r * Dk + d], kxs[d * 96 + j], acc);
        g_proj1[v * 96 + j] = acc;
    }
}

// ---------------------------------------------------------------------------
// Shared layout (bytes). States stored as duplicated (h,h) u64 pairs.
// Partial result buffers: 12 floats per column (16B-aligned float4 stores).
// ---------------------------------------------------------------------------
#define OFF_H1D  0        // [32][8] u64  2048
#define OFF_H2D  2048     // [64][8] u64  4096
#define OFF_P3   6144     // 4 x [192][12] f32 = 4 x 9216
#define OFF_P2   43008    // 2 x [192][12] f32 = 2 x 9216
#define OFF_P1   61440    // 2 x [96][12]  f32 = 2 x 4608
#define OFF_XG1  70656    // 2 x [96][12]  f32 = 9216
#define OFF_TOK  79872    // [8][32] int 1024
#define OFF_BIA3 80896    // 192 f32
#define OFF_BIA2 81664    // 192 f32
#define OFF_BIA1 82432    // 96 f32
#define SMEM_SZ  82816
#define OFF_AGS  6144     // epilogue alias [8][256] f32 (8192)
#define OFF_GWS  14336    // epilogue alias [8][128] f32 (4096)

#define F2(ptr, off) (*(const float2*)&(ptr)[off])

__global__ void __launch_bounds__(NT, 1) rnn_kernel(
    const int*   __restrict__ tokens,
    const float* __restrict__ kh1,   // [32][96]
    const float* __restrict__ b1,    // [2][96]
    const float* __restrict__ kx2,   // [32][192]
    const float* __restrict__ kh2,   // [64][192]
    const float* __restrict__ b2,    // [2][192]
    const float* __restrict__ wg,    // [64][256]
    const float* __restrict__ bg,    // [256]
    const float* __restrict__ wd,    // [128]
    const float* __restrict__ bd,    // [1]
    float*       __restrict__ out)
{
    extern __shared__ char sbuf[];
    u64*   h1d  = (u64*)(sbuf + OFF_H1D);
    u64*   h2d  = (u64*)(sbuf + OFF_H2D);
    float* P3   = (float*)(sbuf + OFF_P3);    // +2304 floats per buf
    float* P2   = (float*)(sbuf + OFF_P2);
    float* P1   = (float*)(sbuf + OFF_P1);    // +1152 floats per buf
    float* xg1  = (float*)(sbuf + OFF_XG1);   // 2 bufs of 1152 floats
    int*   tok  = (int*)(sbuf + OFF_TOK);
    float* bia3 = (float*)(sbuf + OFF_BIA3);
    float* bia2 = (float*)(sbuf + OFF_BIA2);
    float* bia1 = (float*)(sbuf + OFF_BIA1);

    const int tid = threadIdx.x;
    const int b0  = blockIdx.x * BB;

    // ------------- role decode + weights into registers -------------
    // G3 (hm2): tid [0,384):   uh=tid/96 (16u), r=tid%96: bh=r/48, q=r%48 (4 cols)
    // G2 (xg2): tid [384,576): uh=(t)/96 (16u), bh, q (48 quads)
    // G1 (hm1): tid [576,672): uh=(t)/48 (16u), bh=(t%48)/24, q=t%24 (24 quads)
    u64 wq[32];
    int uh = 0, bh = 0, q = 0;
    const float* hbase;            // state read base (byte addr via char*)
    float* obase;                  // partial output base
    const float* biap = 0;         // bias (uh==0 only)
    if (tid < 384) {
        uh = tid / 96; int r = tid % 96; bh = r / 48; q = r % 48;
        #pragma unroll
        for (int uu = 0; uu < 16; uu++) {
            float4 w = *(const float4*)&kh2[(uh * 16 + uu) * 192 + 4 * q];
            wq[2 * uu] = pk2(w.x, w.y); wq[2 * uu + 1] = pk2(w.z, w.w);
        }
        hbase = (const float*)((const char*)h2d + uh * 16 * 64 + bh * 32);
        obase = P3 + uh * 2304 + (4 * q) * 12 + 4 * bh;
        if (uh == 0) biap = bia3 + 4 * q;
    } else if (tid < 576) {
        int t = tid - 384;
        uh = t / 96; int r = t % 96; bh = r / 48; q = r % 48;
        #pragma unroll
        for (int uu = 0; uu < 16; uu++) {
            float4 w = *(const float4*)&kx2[(uh * 16 + uu) * 192 + 4 * q];
            wq[2 * uu] = pk2(w.x, w.y); wq[2 * uu + 1] = pk2(w.z, w.w);
        }
        hbase = (const float*)((const char*)h1d + uh * 16 * 64 + bh * 32);
        obase = P2 + uh * 2304 + (4 * q) * 12 + 4 * bh;
        if (uh == 0) biap = bia2 + 4 * q;
    } else {
        int t = tid - 576;
        uh = t / 48; int r = t % 48; bh = r / 24; q = r % 24;
        #pragma unroll
        for (int uu = 0; uu < 16; uu++) {
            float4 w = *(const float4*)&kh1[(uh * 16 + uu) * 96 + 4 * q];
            wq[2 * uu] = pk2(w.x, w.y); wq[2 * uu + 1] = pk2(w.z, w.w);
        }
        hbase = (const float*)((const char*)h1d + uh * 16 * 64 + bh * 32);
        obase = P1 + uh * 1152 + (4 * q) * 12 + 4 * bh;
        if (uh == 0) biap = bia1 + 4 * q;
    }

    // gather mapping for tid >= 384 (288 threads cover 768 gathers)
    int gi = tid - 384;
    int gb0i = 0, gj0 = 0, gb1i = 0, gj1 = 0, gb2i = 0, gj2 = 0;
    if (gi >= 0) {
        gb0i = gi / 96;          gj0 = gi % 96;
        gb1i = (gi + 288) / 96;  gj1 = (gi + 288) % 96;
        if (gi < 192) { gb2i = (gi + 576) / 96; gj2 = (gi + 576) % 96; }
    }

    // ------------- init: biases, zero states, token chunk 0 -------------
    if (tid < 192) { bia3[tid] = b2[192 + tid]; bia2[tid] = b2[tid]; }
    if (tid >= 192 && tid < 288) bia1[tid - 192] = b1[96 + (tid - 192)];
    for (int i = tid; i < 768; i += NT) ((u64*)sbuf)[i] = 0ull;   // h1d + h2d
    if (tid >= 384 && tid < 640) {
        int t = tid - 384, b = t >> 5, o = t & 31;
        tok[b * 32 + o] = tokens[(b0 + b) * TT + o];
    }
    __syncthreads();
    for (int i = tid; i < 768; i += NT) {
        int b = i / 96, j = i - 96 * (i / 96);
        xg1[0 * 1152 + j * 12 + b] = __ldg(&g_proj1[tok[b * 32 + 0] * 96 + j]);
        xg1[1 * 1152 + j * 12 + b] = __ldg(&g_proj1[tok[b * 32 + 1] * 96 + j]);
    }
    __syncthreads();
    // GRU1 step 0 (h=0): recurrent term is just bias
    if (tid < 128) {
        int u = tid & 31, bo = 2 * (tid >> 5);
        float2 xz = F2(xg1, (u)      * 12 + bo);
        float2 xr = F2(xg1, (32 + u) * 12 + bo);
        float2 xh = F2(xg1, (64 + u) * 12 + bo);
        float bz = bia1[u], br = bia1[32 + u], bhv = bia1[64 + u];
        float n0 = gru1s(xz.x, bz, xr.x, br, xh.x, bhv, 0.0f);
        float n1 = gru1s(xz.y, bz, xr.y, br, xh.y, bhv, 0.0f);
        *(float4*)&h1d[u * 8 + bo] = make_float4(n0, n0, n1, n1);
    }
    __syncthreads();

    float gv0 = 0.0f, gv1 = 0.0f, gv2 = 0.0f;

    #pragma unroll 1
    for (int k = 0; k < TT; k++) {
        // ================= Phase A: gathers + 3 GEMMs =================
        if (gi >= 0 && k < TT - 2) {
            int slot = (k + 2) & 31;
            gv0 = __ldg(&g_proj1[tok[gb0i * 32 + slot] * 96 + gj0]);
            gv1 = __ldg(&g_proj1[tok[gb1i * 32 + slot] * 96 + gj1]);
            if (gi < 192)
                gv2 = __ldg(&g_proj1[tok[gb2i * 32 + slot] * 96 + gj2]);
        }
        {
            u64 a0[4], a1[4];
            u64 bq0 = 0ull, bq1 = 0ull;
            if (biap) {
                float4 bb = *(const float4*)biap;
                bq0 = pk2(bb.x, bb.y); bq1 = pk2(bb.z, bb.w);
            }
            #pragma unroll
            for (int p = 0; p < 4; p++) { a0[p] = bq0; a1[p] = bq1; }
            #pragma unroll
            for (int uu = 0; uu < 16; uu++) {
                ulonglong2 hA = *(const ulonglong2*)((const char*)hbase + uu * 64);
                ulonglong2 hB = *(const ulonglong2*)((const char*)hbase + uu * 64 + 16);
                u64 w0 = wq[2 * uu], w1 = wq[2 * uu + 1];
                a0[0] = ffma2(w0, hA.x, a0[0]); a0[1] = ffma2(w0, hA.y, a0[1]);
                a0[2] = ffma2(w0, hB.x, a0[2]); a0[3] = ffma2(w0, hB.y, a0[3]);
                a1[0] = ffma2(w1, hA.x, a1[0]); a1[1] = ffma2(w1, hA.y, a1[1]);
                a1[2] = ffma2(w1, hB.x, a1[2]); a1[3] = ffma2(w1, hB.y, a1[3]);
            }
            // transpose: lanes are columns -> store per-column float4 of batches
            float c00, c10, c01, c11, c02, c12, c03, c13;
            upk2(a0[0], c00, c10); upk2(a0[1], c01, c11);
            upk2(a0[2], c02, c12); upk2(a0[3], c03, c13);
            *(float4*)&obase[0]  = make_float4(c00, c01, c02, c03);
            *(float4*)&obase[12] = make_float4(c10, c11, c12, c13);
            upk2(a1[0], c00, c10); upk2(a1[1], c01, c11);
            upk2(a1[2], c02, c12); upk2(a1[3], c03, c13);
            *(float4*)&obase[24] = make_float4(c00, c01, c02, c03);
            *(float4*)&obase[36] = make_float4(c10, c11, c12, c13);
        }
        __syncthreads();

        // ================= Phase B: gates (384 thr) + stores =================
        if (tid < 256) {
            // GRU2 gates, step k: one batch pair each
            int u = tid & 63, bo = 2 * (tid >> 6);
            int cz = u * 12 + bo, cr = (64 + u) * 12 + bo, ch = (128 + u) * 12 + bo;
            float2 x0, x1, s0, s1, s2, s3;
            x0 = F2(P2, cz); x1 = F2(P2 + 2304, cz);
            float xz0 = x0.x + x1.x, xz1 = x0.y + x1.y;
            x0 = F2(P2, cr); x1 = F2(P2 + 2304, cr);
            float xr0 = x0.x + x1.x, xr1 = x0.y + x1.y;
            x0 = F2(P2, ch); x1 = F2(P2 + 2304, ch);
            float xh0 = x0.x + x1.x, xh1 = x0.y + x1.y;
            s0 = F2(P3, cz); s1 = F2(P3 + 2304, cz); s2 = F2(P3 + 4608, cz); s3 = F2(P3 + 6912, cz);
            float hz0 = (s0.x + s1.x) + (s2.x + s3.x), hz1 = (s0.y + s1.y) + (s2.y + s3.y);
            s0 = F2(P3, cr); s1 = F2(P3 + 2304, cr); s2 = F2(P3 + 4608, cr); s3 = F2(P3 + 6912, cr);
            float hr0 = (s0.x + s1.x) + (s2.x + s3.x), hr1 = (s0.y + s1.y) + (s2.y + s3.y);
            s0 = F2(P3, ch); s1 = F2(P3 + 2304, ch); s2 = F2(P3 + 4608, ch); s3 = F2(P3 + 6912, ch);
            float hh0 = (s0.x + s1.x) + (s2.x + s3.x), hh1 = (s0.y + s1.y) + (s2.y + s3.y);
            float4 hv = *(const float4*)&h2d[u * 8 + bo];
            float n0 = gru1s(xz0, hz0, xr0, hr0, xh0, hh0, hv.x);
            float n1 = gru1s(xz1, hz1, xr1, hr1, xh1, hh1, hv.z);
            *(float4*)&h2d[u * 8 + bo] = make_float4(n0, n0, n1, n1);
        } else if (tid < 384) {
            // GRU1 gates, step k+1
            if (k < TT - 1) {
                int t2 = tid - 256;
                int u = t2 & 31, bo = 2 * (t2 >> 5);
                const float* xb = xg1 + ((k + 1) & 1) * 1152;
                int cz = u * 12 + bo, cr = (32 + u) * 12 + bo, ch = (64 + u) * 12 + bo;
                float2 xzv = F2(xb, cz), xrv = F2(xb, cr), xhv = F2(xb, ch);
                float2 p0, p1;
                p0 = F2(P1, cz); p1 = F2(P1 + 1152, cz);
                float hz0 = p0.x + p1.x, hz1 = p0.y + p1.y;
                p0 = F2(P1, cr); p1 = F2(P1 + 1152, cr);
                float hr0 = p0.x + p1.x, hr1 = p0.y + p1.y;
                p0 = F2(P1, ch); p1 = F2(P1 + 1152, ch);
                float hh0 = p0.x + p1.x, hh1 = p0.y + p1.y;
                float4 hv = *(const float4*)&h1d[u * 8 + bo];
                float n0 = gru1s(xzv.x, hz0, xrv.x, hr0, xhv.x, hh0, hv.x);
                float n1 = gru1s(xzv.y, hz1, xrv.y, hr1, xhv.y, hh1, hv.z);
                *(float4*)&h1d[u * 8 + bo] = make_float4(n0, n0, n1, n1);
            }
        }
        if (gi >= 0) {
            if (k < TT - 2) {
                float* xb = xg1 + ((k + 2) & 1) * 1152;
                xb[gj0 * 12 + gb0i] = gv0;
                xb[gj1 * 12 + gb1i] = gv1;
                if (gi < 192) xb[gj2 * 12 + gb2i] = gv2;
            }
            if (((k + 3) & 31) == 0 && (k + 3) < TT && gi < 256) {
                int b = gi >> 5, o = gi & 31;
                tok[b * 32 + o] = tokens[(b0 + b) * TT + (k + 3) + o];
            }
        }
        __syncthreads();
    }

    // ================= Epilogue: GLU + dense + sigmoid =================
    float* ags = (float*)(sbuf + OFF_AGS);   // [8][256]
    float* gws = (float*)(sbuf + OFF_GWS);   // [8][128]
    if (tid < 256) {
        int c = tid;
        float bgv = bg[c];
        u64 acc0 = pk2(bgv, bgv), acc1 = acc0, acc2 = acc0, acc3 = acc0;
        #pragma unroll
        for (int u = 0; u < 64; u++) {
            const float4* hp = (const float4*)&h2d[u * 8];
            float4 v01 = hp[0], v23 = hp[1], v45 = hp[2], v67 = hp[3];
            float wv = __ldg(&wg[u * 256 + c]);
            u64 w = pk2(wv, wv);
            acc0 = ffma2(w, pk2(v01.x, v01.z), acc0);
            acc1 = ffma2(w, pk2(v23.x, v23.z), acc1);
            acc2 = ffma2(w, pk2(v45.x, v45.z), acc2);
            acc3 = ffma2(w, pk2(v67.x, v67.z), acc3);
        }
        float f0, f1;
        upk2(acc0, f0, f1); ags[0 * 256 + c] = f0; ags[1 * 256 + c] = f1;
        upk2(acc1, f0, f1); ags[2 * 256 + c] = f0; ags[3 * 256 + c] = f1;
        upk2(acc2, f0, f1); ags[4 * 256 + c] = f0; ags[5 * 256 + c] = f1;
        upk2(acc3, f0, f1); ags[6 * 256 + c] = f0; ags[7 * 256 + c] = f1;
    }
    __syncthreads();
    for (int i = tid; i < 1024; i += NT) {
        int b = i >> 7, kk = i & 127;
        float g = ags[b * 256 + kk] * sgm(ags[b * 256 + 128 + kk]);
        gws[b * 128 + kk] = g * __ldg(&wd[kk]);
    }
    __syncthreads();
    if (tid < BB) {
        float s = bd[0];
        #pragma unroll
        for (int kk = 0; kk < 128; kk++) s += gws[tid * 128 + kk];
        out[b0 + tid] = sgm(s);
    }
}

// ---------------------------------------------------------------------------
extern "C" void kernel_launch(void* const* d_in, const int* in_sizes, int n_in,
                              void* d_out, int out_size) {
    (void)in_sizes; (void)n_in; (void)out_size;
    const int*   tokens = (const int*)  d_in[0];
    const float* emb    = (const float*)d_in[1];
    const float* kx1    = (const float*)d_in[2];
    const float* kh1    = (const float*)d_in[3];
    const float* b1     = (const float*)d_in[4];
    const float* kx2    = (const float*)d_in[5];
    const float* kh2    = (const float*)d_in[6];
    const float* b2     = (const float*)d_in[7];
    const float* wg     = (const float*)d_in[8];
    const float* bg     = (const float*)d_in[9];
    const float* wd     = (const float*)d_in[10];
    const float* bd     = (const float*)d_in[11];

    static int smem_set = 0;
    if (!smem_set) {
        cudaFuncSetAttribute(rnn_kernel,
                             cudaFuncAttributeMaxDynamicSharedMemorySize, SMEM_SZ);
        smem_set = 1;
    }

    proj_kernel<<<(VSZ + 15) / 16, 256>>>(emb, kx1, b1);
    rnn_kernel<<<BSZ / BB, NT, SMEM_SZ>>>(tokens, kh1, b1, kx2, kh2, b2,
                                          wg, bg, wd, bd, (float*)d_out);
}

// round 8
// speedup vs baseline: 1.1098x; 1.1098x over previous
#include <cuda_runtime.h>

#define VSZ 50257
#define Dk  50
#define TT  1024
#define BSZ 1024
#define BB  8
#define NT  672

// Precomputed emb @ kx1 + b1[0] table: [V, 96] fp32 (L2-resident, 19.3MB)
__device__ float g_proj1[VSZ * 96];

typedef unsigned long long u64;

__device__ __forceinline__ u64 pk2(float a, float b) {
    u64 r; asm("mov.b64 %0, {%1, %2};" : "=l"(r) : "f"(a), "f"(b)); return r;
}
__device__ __forceinline__ void upk2(u64 v, float& a, float& b) {
    asm("mov.b64 {%0, %1}, %2;" : "=f"(a), "=f"(b) : "l"(v));
}
__device__ __forceinline__ u64 ffma2(u64 a, u64 b, u64 c) {
    u64 d; asm("fma.rn.f32x2 %0, %1, %2, %3;" : "=l"(d) : "l"(a), "l"(b), "l"(c)); return d;
}
__device__ __forceinline__ float sgm(float x) { return 1.0f / (1.0f + __expf(-x)); }
__device__ __forceinline__ float tnh(float x) { return 2.0f * sgm(2.0f * x) - 1.0f; }

__device__ __forceinline__ float gru1s(float xz, float hz, float xr, float hr,
                                       float xh, float hh, float hold) {
    float z = sgm(xz + hz);
    float r = sgm(xr + hr);
    float c = tnh(xh + r * hh);
    return z * hold + (1.0f - z) * c;
}

// ---------------------------------------------------------------------------
__global__ void proj_kernel(const float* __restrict__ emb,
                            const float* __restrict__ kx1,
                            const float* __restrict__ b1) {
    __shared__ float kxs[Dk * 96];
    __shared__ float embs[16 * Dk];
    int tid = threadIdx.x;
    for (int i = tid; i < Dk * 96; i += 256) kxs[i] = kx1[i];
    int vbase = blockIdx.x * 16;
    for (int i = tid; i < 16 * Dk; i += 256) {
        int r = i / Dk, d = i - r * Dk;
        int v = vbase + r;
        embs[i] = (v < VSZ) ? emb[v * Dk + d] : 0.0f;
    }
    __syncthreads();
    for (int i = tid; i < 16 * 96; i += 256) {
        int r = i / 96, j = i - r * 96;
        int v = vbase + r;
        if (v >= VSZ) continue;
        float acc = b1[j];
        #pragma unroll
        for (int d = 0; d < Dk; d++)
            acc = fmaf(embs[r * Dk + d], kxs[d * 96 + j], acc);
        g_proj1[v * 96 + j] = acc;
    }
}

// ---------------------------------------------------------------------------
// Shared layout (bytes).
// States: [u][10] u64 rows (80B padded, 16B-aligned; entries are dup (h,h)).
//   GEMM reads: 16B broadcast chunks (aligned). Gate u64 writes: deg-4 only.
// P partial buffers: [buf][batch(8)][cols] f32.
//   GEMM stores: u64 at [b][2q], lanes q consecutive -> conflict-free.
//   Gate reads: [2c][u], lanes u consecutive -> coalesced LDS.32.
// ---------------------------------------------------------------------------
#define OFF_H1S  0        // 32*10 u64 = 2560
#define OFF_H2S  2560     // 64*10 u64 = 5120
#define OFF_P3   7680     // 4 bufs x [8][192] f32 = 4*6144
#define OFF_P2   32256    // 2 bufs x [8][192] f32 = 2*6144
#define OFF_P1   44544    // 2 bufs x [8][96]  f32 = 2*3072
#define OFF_XG1  50688    // 2 bufs x [8][96]  f32 = 2*3072
#define OFF_TOK  56832    // [8][32] int = 1024
#define SMEM_SZ  57856

__global__ void __launch_bounds__(NT, 1) rnn_kernel(
    const int*   __restrict__ tokens,
    const float* __restrict__ kh1,   // [32][96]
    const float* __restrict__ b1,    // [2][96]
    const float* __restrict__ kx2,   // [32][192]
    const float* __restrict__ kh2,   // [64][192]
    const float* __restrict__ b2,    // [2][192]
    const float* __restrict__ wg,    // [64][256]
    const float* __restrict__ bg,    // [256]
    const float* __restrict__ wd,    // [128]
    const float* __restrict__ bd,    // [1]
    float*       __restrict__ out)
{
    extern __shared__ char sbuf[];
    u64*   h1s = (u64*)(sbuf + OFF_H1S);   // [u][10]
    u64*   h2s = (u64*)(sbuf + OFF_H2S);   // [u][10]
    float* P3f = (float*)(sbuf + OFF_P3);  // bufs stride 1536 floats
    float* P2f = (float*)(sbuf + OFF_P2);
    float* P1f = (float*)(sbuf + OFF_P1);  // bufs stride 768 floats
    float* xg1 = (float*)(sbuf + OFF_XG1); // bufs stride 768 floats
    int*   tok = (int*)(sbuf + OFF_TOK);

    const int tid = threadIdx.x;
    const int b0  = blockIdx.x * BB;

    // ------------- role decode + weights into registers -------------
    // G3 (hm2=h2@kh2): tid [0,384):   uh=tid/96 (16u), bh=(tid%96)/48, q=tid%48
    // G2 (xg2=h1@kx2): tid [384,576): uh, bh, q (48)
    // G1 (hm1=h1@kh1): tid [576,672): uh=t/48,  bh=(t%48)/24, q=t%24
    u64 wA[16], wB[16];
    u64 bqA = 0ull, bqB = 0ull;
    const char* sread;   // state read base for this thread's uu loop
    float* oA;           // P store base (float index at [4bh][2q])
    int rowl, coffs;
    {
        const float* wsrc; const float* bsrc; const char* stateb; float* pbase;
        int uh, bh, q, ncols, plen;
        if (tid < 384) {
            uh = tid / 96; int r = tid % 96; bh = r / 48; q = r % 48;
            wsrc = kh2; bsrc = b2 + 192; stateb = sbuf + OFF_H2S;
            ncols = 192; coffs = 96; pbase = P3f + uh * 1536; plen = 192;
        } else if (tid < 576) {
            int t = tid - 384;
            uh = t / 96; int r = t % 96; bh = r / 48; q = r % 48;
            wsrc = kx2; bsrc = b2; stateb = sbuf + OFF_H1S;
            ncols = 192; coffs = 96; pbase = P2f + uh * 1536; plen = 192;
        } else {
            int t = tid - 576;
            uh = t / 48; int r = t % 48; bh = r / 24; q = r % 24;
            wsrc = kh1; bsrc = b1 + 96; stateb = sbuf + OFF_H1S;
            ncols = 96; coffs = 48; pbase = P1f + uh * 768; plen = 96;
        }
        int u0 = uh * 16;
        #pragma unroll
        for (int uu = 0; uu < 16; uu++) {
            float2 a = *(const float2*)&wsrc[(u0 + uu) * ncols + 2 * q];
            float2 b = *(const float2*)&wsrc[(u0 + uu) * ncols + 2 * q + coffs];
            wA[uu] = pk2(a.x, a.y); wB[uu] = pk2(b.x, b.y);
        }
        if (uh == 0) {
            float2 a = *(const float2*)&bsrc[2 * q];
            float2 b = *(const float2*)&bsrc[2 * q + coffs];
            bqA = pk2(a.x, a.y); bqB = pk2(b.x, b.y);
        }
        sread = stateb + u0 * 80 + 4 * bh * 8;   // 16B-aligned (80 % 16 == 0)
        oA = pbase + (4 * bh) * plen + 2 * q;
        rowl = plen;
    }

    // gather mapping (tid >= 384: 288 threads cover 768 gathers, linear index)
    const int gi = tid - 384;
    int gb0 = 0, gj0 = 0, gb1 = 0, gj1 = 0, gb2 = 0, gj2 = 0;
    if (gi >= 0) {
        gb0 = gi / 96;          gj0 = gi % 96;
        gb1 = (gi + 288) / 96;  gj1 = (gi + 288) % 96;
        gb2 = (gi + 576) / 96;  gj2 = (gi + 576) % 96;
    }

    // ------------- init: zero states, token chunk 0 -------------
    for (int i = tid; i < 960; i += NT) ((u64*)sbuf)[i] = 0ull;  // h1s + h2s
    if (gi >= 0 && gi < 256) {
        int b = gi >> 5, o = gi & 31;
        tok[b * 32 + o] = tokens[(b0 + b) * TT + o];
    }
    __syncthreads();
    // prefill xg1 for t=0 (buf0), t=1 (buf1); layout [b][96] = linear
    for (int i = tid; i < 768; i += NT) {
        int b = i / 96, j = i - 96 * (i / 96);
        xg1[i]       = __ldg(&g_proj1[tok[b * 32 + 0] * 96 + j]);
        xg1[768 + i] = __ldg(&g_proj1[tok[b * 32 + 1] * 96 + j]);
    }
    __syncthreads();
    // GRU1 step 0 (h=0 -> recurrent term = bias)
    if (tid < 128) {
        int u = tid & 31, c = tid >> 5;
        int r0 = (2 * c) * 96 + u, r1 = r0 + 96;
        float bz = b1[96 + u], br = b1[128 + u], bhv = b1[160 + u];
        float n0 = gru1s(xg1[r0], bz, xg1[r0 + 32], br, xg1[r0 + 64], bhv, 0.0f);
        float n1 = gru1s(xg1[r1], bz, xg1[r1 + 32], br, xg1[r1 + 64], bhv, 0.0f);
        h1s[u * 10 + 2 * c]     = pk2(n0, n0);
        h1s[u * 10 + 2 * c + 1] = pk2(n1, n1);
    }
    __syncthreads();

    float gv0 = 0.0f, gv1 = 0.0f, gv2 = 0.0f;

    #pragma unroll 1
    for (int k = 0; k < TT; k++) {
        // ================= Phase A: gathers + 3 GEMMs =================
        if (gi >= 0 && k < TT - 2) {
            int slot = (k + 2) & 31;
            gv0 = __ldg(&g_proj1[tok[gb0 * 32 + slot] * 96 + gj0]);
            gv1 = __ldg(&g_proj1[tok[gb1 * 32 + slot] * 96 + gj1]);
            if (gi < 192)
                gv2 = __ldg(&g_proj1[tok[gb2 * 32 + slot] * 96 + gj2]);
        }
        {
            u64 aA0 = bqA, aA1 = bqA, aA2 = bqA, aA3 = bqA;
            u64 aB0 = bqB, aB1 = bqB, aB2 = bqB, aB3 = bqB;
            #pragma unroll
            for (int uu = 0; uu < 16; uu++) {
                // batches 4bh..4bh+3, dup u64 each; 80B row stride (aligned)
                ulonglong2 hA = *(const ulonglong2*)(sread + uu * 80);
                ulonglong2 hB = *(const ulonglong2*)(sread + uu * 80 + 16);
                u64 w0 = wA[uu], w1 = wB[uu];
                aA0 = ffma2(w0, hA.x, aA0); aA1 = ffma2(w0, hA.y, aA1);
                aB0 = ffma2(w1, hA.x, aB0); aB1 = ffma2(w1, hA.y, aB1);
                aA2 = ffma2(w0, hB.x, aA2); aA3 = ffma2(w0, hB.y, aA3);
                aB2 = ffma2(w1, hB.x, aB2); aB3 = ffma2(w1, hB.y, aB3);
            }
            // conflict-free u64 stores: [b][col], lanes q consecutive
            *(u64*)&oA[0]            = aA0;
            *(u64*)&oA[rowl]         = aA1;
            *(u64*)&oA[2 * rowl]     = aA2;
            *(u64*)&oA[3 * rowl]     = aA3;
            *(u64*)&oA[coffs]            = aB0;
            *(u64*)&oA[rowl + coffs]     = aB1;
            *(u64*)&oA[2 * rowl + coffs] = aB2;
            *(u64*)&oA[3 * rowl + coffs] = aB3;
        }
        __syncthreads();

        // ================= Phase B: gates + gather stores =================
        if (tid < 256) {
            // GRU2 gates, step k: thread = (u=lane, c), batches 2c, 2c+1
            int u = tid & 63, c = tid >> 6;
            int r0 = (2 * c) * 192 + u, r1 = r0 + 192;
            #define PS2(PF, idx) (PF[(idx)] + PF[1536 + (idx)])
            #define PS4(PF, idx) ((PF[(idx)] + PF[1536 + (idx)]) + (PF[3072 + (idx)] + PF[4608 + (idx)]))
            float xz0 = PS2(P2f, r0),       xz1 = PS2(P2f, r1);
            float xr0 = PS2(P2f, r0 + 64),  xr1 = PS2(P2f, r1 + 64);
            float xh0 = PS2(P2f, r0 + 128), xh1 = PS2(P2f, r1 + 128);
            float hz0 = PS4(P3f, r0),       hz1 = PS4(P3f, r1);
            float hr0 = PS4(P3f, r0 + 64),  hr1 = PS4(P3f, r1 + 64);
            float hh0 = PS4(P3f, r0 + 128), hh1 = PS4(P3f, r1 + 128);
            float o0, o1, dummy;
            upk2(h2s[u * 10 + 2 * c], o0, dummy);
            upk2(h2s[u * 10 + 2 * c + 1], o1, dummy);
            float n0 = gru1s(xz0, hz0, xr0, hr0, xh0, hh0, o0);
            float n1 = gru1s(xz1, hz1, xr1, hr1, xh1, hh1, o1);
            h2s[u * 10 + 2 * c]     = pk2(n0, n0);
            h2s[u * 10 + 2 * c + 1] = pk2(n1, n1);
        } else if (tid < 384) {
            // GRU1 gates, step k+1
            if (k < TT - 1) {
                int t2 = tid - 256;
                int u = t2 & 31, c = t2 >> 5;
                const float* xb = xg1 + ((k + 1) & 1) * 768;
                int r0 = (2 * c) * 96 + u, r1 = r0 + 96;
                #define PS21(PF, idx) (PF[(idx)] + PF[768 + (idx)])
                float hz0 = PS21(P1f, r0),      hz1 = PS21(P1f, r1);
                float hr0 = PS21(P1f, r0 + 32), hr1 = PS21(P1f, r1 + 32);
                float hh0 = PS21(P1f, r0 + 64), hh1 = PS21(P1f, r1 + 64);
                float o0, o1, dummy;
                upk2(h1s[u * 10 + 2 * c], o0, dummy);
                upk2(h1s[u * 10 + 2 * c + 1], o1, dummy);
                float n0 = gru1s(xb[r0], hz0, xb[r0 + 32], hr0, xb[r0 + 64], hh0, o0);
                float n1 = gru1s(xb[r1], hz1, xb[r1 + 32], hr1, xb[r1 + 64], hh1, o1);
                h1s[u * 10 + 2 * c]     = pk2(n0, n0);
                h1s[u * 10 + 2 * c + 1] = pk2(n1, n1);
            }
        }
        if (gi >= 0) {
            if (k < TT - 2) {
                float* xb = xg1 + ((k + 2) & 1) * 768;
                xb[gi] = gv0;
                xb[gi + 288] = gv1;
                if (gi < 192) xb[gi + 576] = gv2;
            }
            if (((k + 3) & 31) == 0 && (k + 3) < TT && gi < 256) {
                int b = gi >> 5, o = gi & 31;
                tok[b * 32 + o] = tokens[(b0 + b) * TT + (k + 3) + o];
            }
        }
        __syncthreads();
    }

    // ================= Epilogue: GLU + dense + sigmoid =================
    float* ags = P3f;   // [8][256] alias
    float* gws = P2f;   // [8][128] alias
    if (tid < 256) {
        int c = tid;
        float bgv = bg[c];
        u64 acc0 = pk2(bgv, bgv), acc1 = acc0, acc2 = acc0, acc3 = acc0;
        #pragma unroll
        for (int u = 0; u < 64; u++) {
            const u64* hr = h2s + u * 10;
            float wv = __ldg(&wg[u * 256 + c]);
            u64 w = pk2(wv, wv);
            float f0, f1, f2, f3, d_;
            upk2(hr[0], f0, d_); upk2(hr[1], f1, d_);
            upk2(hr[2], f2, d_); upk2(hr[3], f3, d_);
            acc0 = ffma2(w, pk2(f0, f1), acc0);
            acc1 = ffma2(w, pk2(f2, f3), acc1);
            upk2(hr[4], f0, d_); upk2(hr[5], f1, d_);
            upk2(hr[6], f2, d_); upk2(hr[7], f3, d_);
            acc2 = ffma2(w, pk2(f0, f1), acc2);
            acc3 = ffma2(w, pk2(f2, f3), acc3);
        }
        float f0, f1;
        upk2(acc0, f0, f1); ags[0 * 256 + c] = f0; ags[1 * 256 + c] = f1;
        upk2(acc1, f0, f1); ags[2 * 256 + c] = f0; ags[3 * 256 + c] = f1;
        upk2(acc2, f0, f1); ags[4 * 256 + c] = f0; ags[5 * 256 + c] = f1;
        upk2(acc3, f0, f1); ags[6 * 256 + c] = f0; ags[7 * 256 + c] = f1;
    }
    __syncthreads();
    for (int i = tid; i < 1024; i += NT) {
        int b = i >> 7, kk = i & 127;
        float g = ags[b * 256 + kk] * sgm(ags[b * 256 + 128 + kk]);
        gws[b * 128 + kk] = g * __ldg(&wd[kk]);
    }
    __syncthreads();
    if (tid < BB) {
        float s = bd[0];
        #pragma unroll
        for (int kk = 0; kk < 128; kk++) s += gws[tid * 128 + kk];
        out[b0 + tid] = sgm(s);
    }
}

// ---------------------------------------------------------------------------
extern "C" void kernel_launch(void* const* d_in, const int* in_sizes, int n_in,
                              void* d_out, int out_size) {
    (void)in_sizes; (void)n_in; (void)out_size;
    const int*   tokens = (const int*)  d_in[0];
    const float* emb    = (const float*)d_in[1];
    const float* kx1    = (const float*)d_in[2];
    const float* kh1    = (const float*)d_in[3];
    const float* b1     = (const float*)d_in[4];
    const float* kx2    = (const float*)d_in[5];
    const float* kh2    = (const float*)d_in[6];
    const float* b2     = (const float*)d_in[7];
    const float* wg     = (const float*)d_in[8];
    const float* bg     = (const float*)d_in[9];
    const float* wd     = (const float*)d_in[10];
    const float* bd     = (const float*)d_in[11];

    static int smem_set = 0;
    if (!smem_set) {
        cudaFuncSetAttribute(rnn_kernel,
                             cudaFuncAttributeMaxDynamicSharedMemorySize, SMEM_SZ);
        smem_set = 1;
    }

    proj_kernel<<<(VSZ + 15) / 16, 256>>>(emb, kx1, b1);
    rnn_kernel<<<BSZ / BB, NT, SMEM_SZ>>>(tokens, kh1, b1, kx2, kh2, b2,
                                          wg, bg, wd, bd, (float*)d_out);
}

// round 9
// speedup vs baseline: 1.2038x; 1.0847x over previous
#include <cuda_runtime.h>

#define VSZ 50257
#define Dk  50
#define TT  1024
#define BSZ 1024
#define BB  4
#define NT  336

// Precomputed emb @ kx1 + b1[0] table: [V, 96] fp32 (L2-resident, 19.3MB)
__device__ float g_proj1[VSZ * 96];

typedef unsigned long long u64;

__device__ __forceinline__ u64 pk2(float a, float b) {
    u64 r; asm("mov.b64 %0, {%1, %2};" : "=l"(r) : "f"(a), "f"(b)); return r;
}
__device__ __forceinline__ void upk2(u64 v, float& a, float& b) {
    asm("mov.b64 {%0, %1}, %2;" : "=f"(a), "=f"(b) : "l"(v));
}
__device__ __forceinline__ u64 ffma2(u64 a, u64 b, u64 c) {
    u64 d; asm("fma.rn.f32x2 %0, %1, %2, %3;" : "=l"(d) : "l"(a), "l"(b), "l"(c)); return d;
}
__device__ __forceinline__ float sgm(float x) { return 1.0f / (1.0f + __expf(-x)); }
__device__ __forceinline__ float tnh(float x) { return 2.0f * sgm(2.0f * x) - 1.0f; }

__device__ __forceinline__ float gru1s(float xz, float hz, float xr, float hr,
                                       float xh, float hh, float hold) {
    float z = sgm(xz + hz);
    float r = sgm(xr + hr);
    float c = tnh(xh + r * hh);
    return z * hold + (1.0f - z) * c;
}

// ---------------------------------------------------------------------------
__global__ void proj_kernel(const float* __restrict__ emb,
                            const float* __restrict__ kx1,
                            const float* __restrict__ b1) {
    __shared__ float kxs[Dk * 96];
    __shared__ float embs[16 * Dk];
    int tid = threadIdx.x;
    for (int i = tid; i < Dk * 96; i += 256) kxs[i] = kx1[i];
    int vbase = blockIdx.x * 16;
    for (int i = tid; i < 16 * Dk; i += 256) {
        int r = i / Dk, d = i - r * Dk;
        int v = vbase + r;
        embs[i] = (v < VSZ) ? emb[v * Dk + d] : 0.0f;
    }
    __syncthreads();
    for (int i = tid; i < 16 * 96; i += 256) {
        int r = i / 96, j = i - r * 96;
        int v = vbase + r;
        if (v >= VSZ) continue;
        float acc = b1[j];
        #pragma unroll
        for (int d = 0; d < Dk; d++)
            acc = fmaf(embs[r * Dk + d], kxs[d * 96 + j], acc);
        g_proj1[v * 96 + j] = acc;
    }
}

// ---------------------------------------------------------------------------
// Shared layout (bytes), BB=4 batches per CTA.
// States: [u][6] u64 rows (48B, 16B-aligned; entries are dup pairs (h,h),
//   slots 0..3 = batches 0..3). GEMM reads 16B broadcast; gate writes deg-4.
// P partial buffers: [buf][batch(4)][cols] f32.
//   GEMM stores: u64 at [b][2q], lanes q consecutive -> conflict-free.
//   Gate reads: [2c][u], lanes u consecutive -> coalesced LDS.32.
// ---------------------------------------------------------------------------
#define OFF_H1S  0        // 32*6 u64 = 1536
#define OFF_H2S  1536     // 64*6 u64 = 3072
#define OFF_P3   4608     // 4 bufs x [4][192] f32 = 4*3072
#define OFF_P2   16896    // 2 bufs x [4][192] f32 = 2*3072
#define OFF_P1   23040    // 2 bufs x [4][96]  f32 = 2*1536
#define OFF_XG1  26112    // 2 bufs x [4][96]  f32 = 2*1536
#define OFF_TOK  29184    // [4][32] int = 512
#define SMEM_SZ  29696

__global__ void __launch_bounds__(NT, 2) rnn_kernel(
    const int*   __restrict__ tokens,
    const float* __restrict__ kh1,   // [32][96]
    const float* __restrict__ b1,    // [2][96]
    const float* __restrict__ kx2,   // [32][192]
    const float* __restrict__ kh2,   // [64][192]
    const float* __restrict__ b2,    // [2][192]
    const float* __restrict__ wg,    // [64][256]
    const float* __restrict__ bg,    // [256]
    const float* __restrict__ wd,    // [128]
    const float* __restrict__ bd,    // [1]
    float*       __restrict__ out)
{
    extern __shared__ char sbuf[];
    u64*   h1s = (u64*)(sbuf + OFF_H1S);   // [u][6]
    u64*   h2s = (u64*)(sbuf + OFF_H2S);   // [u][6]
    float* P3f = (float*)(sbuf + OFF_P3);  // bufs stride 768 floats
    float* P2f = (float*)(sbuf + OFF_P2);  // bufs stride 768 floats
    float* P1f = (float*)(sbuf + OFF_P1);  // bufs stride 384 floats
    float* xg1 = (float*)(sbuf + OFF_XG1); // bufs stride 384 floats
    int*   tok = (int*)(sbuf + OFF_TOK);

    const int tid = threadIdx.x;
    const int b0  = blockIdx.x * BB;

    // ------------- role decode + weights into registers -------------
    // G3 (hm2=h2@kh2): tid [0,192):   uh=tid/48 (4 x 16u), q=tid%48
    // G2 (xg2=h1@kx2): tid [192,288): uh=t/48 (2 x 16u),   q=t%48
    // G1 (hm1=h1@kh1): tid [288,336): uh=t/24 (2 x 16u),   q=t%24
    // Each thread: 4 cols (2q,2q+1, 2q+coffs,2q+coffs+1) x 4 batches x 16u.
    u64 wA[16], wB[16];
    u64 bqA = 0ull, bqB = 0ull;
    const char* sread;
    float* oA;
    int coffs;
    {
        const float* wsrc; const float* bsrc; const char* stateb; float* pbase;
        int uh, q, ncols;
        if (tid < 192) {
            uh = tid / 48; q = tid % 48;
            wsrc = kh2; bsrc = b2 + 192; stateb = sbuf + OFF_H2S;
            ncols = 192; coffs = 96; pbase = P3f + uh * 768;
        } else if (tid < 288) {
            int t = tid - 192;
            uh = t / 48; q = t % 48;
            wsrc = kx2; bsrc = b2; stateb = sbuf + OFF_H1S;
            ncols = 192; coffs = 96; pbase = P2f + uh * 768;
        } else {
            int t = tid - 288;
            uh = t / 24; q = t % 24;
            wsrc = kh1; bsrc = b1 + 96; stateb = sbuf + OFF_H1S;
            ncols = 96; coffs = 48; pbase = P1f + uh * 384;
        }
        int u0 = uh * 16;
        #pragma unroll
        for (int uu = 0; uu < 16; uu++) {
            float2 a = *(const float2*)&wsrc[(u0 + uu) * ncols + 2 * q];
            float2 b = *(const float2*)&wsrc[(u0 + uu) * ncols + 2 * q + coffs];
            wA[uu] = pk2(a.x, a.y); wB[uu] = pk2(b.x, b.y);
        }
        if (uh == 0) {
            float2 a = *(const float2*)&bsrc[2 * q];
            float2 b = *(const float2*)&bsrc[2 * q + coffs];
            bqA = pk2(a.x, a.y); bqB = pk2(b.x, b.y);
        }
        sread = stateb + u0 * 48;           // 16B-aligned (48 % 16 == 0)
        oA = pbase + 2 * q;
    }
    const int rowl = (tid < 288) ? 192 : 96;

    // gather mapping (tid in [192,336): 144 threads cover 384 gathers)
    const int gi = tid - 192;
    int gb0 = 0, gj0 = 0, gb1 = 0, gj1 = 0;
    if (gi >= 0) {
        gb0 = gi / 96;          gj0 = gi % 96;
        gb1 = (gi + 144) / 96;  gj1 = (gi + 144) % 96;
        // third gather (gi < 96): batch 3, col gi
    }

    // ------------- init: zero states, token chunk 0 -------------
    for (int i = tid; i < 576; i += NT) ((u64*)sbuf)[i] = 0ull;  // h1s + h2s
    if (gi >= 0 && gi < 128) {
        int b = gi >> 5, o = gi & 31;
        tok[b * 32 + o] = tokens[(b0 + b) * TT + o];
    }
    __syncthreads();
    // prefill xg1 for t=0 (buf0), t=1 (buf1); layout [b][96] linear
    for (int i = tid; i < 384; i += NT) {
        int b = i / 96, j = i - 96 * (i / 96);
        xg1[i]       = __ldg(&g_proj1[tok[b * 32 + 0] * 96 + j]);
        xg1[384 + i] = __ldg(&g_proj1[tok[b * 32 + 1] * 96 + j]);
    }
    __syncthreads();
    // GRU1 step 0 (h=0 -> recurrent term = bias)
    if (tid < 64) {
        int u = tid & 31, c = tid >> 5;
        int r0 = (2 * c) * 96 + u, r1 = r0 + 96;
        float bz = b1[96 + u], br = b1[128 + u], bhv = b1[160 + u];
        float n0 = gru1s(xg1[r0], bz, xg1[r0 + 32], br, xg1[r0 + 64], bhv, 0.0f);
        float n1 = gru1s(xg1[r1], bz, xg1[r1 + 32], br, xg1[r1 + 64], bhv, 0.0f);
        h1s[u * 6 + 2 * c]     = pk2(n0, n0);
        h1s[u * 6 + 2 * c + 1] = pk2(n1, n1);
    }
    __syncthreads();

    float gv0 = 0.0f, gv1 = 0.0f, gv2 = 0.0f;

    #pragma unroll 1
    for (int k = 0; k < TT; k++) {
        // ================= Phase A: gathers + 3 GEMMs =================
        if (gi >= 0 && k < TT - 2) {
            int slot = (k + 2) & 31;
            gv0 = __ldg(&g_proj1[tok[gb0 * 32 + slot] * 96 + gj0]);
            gv1 = __ldg(&g_proj1[tok[gb1 * 32 + slot] * 96 + gj1]);
            if (gi < 96)
                gv2 = __ldg(&g_proj1[tok[3 * 32 + slot] * 96 + gi]);
        }
        {
            u64 aA0 = bqA, aA1 = bqA, aA2 = bqA, aA3 = bqA;
            u64 aB0 = bqB, aB1 = bqB, aB2 = bqB, aB3 = bqB;
            #pragma unroll
            for (int uu = 0; uu < 16; uu++) {
                // batches 0..3, dup u64 each; 48B row stride (16B-aligned)
                ulonglong2 hA = *(const ulonglong2*)(sread + uu * 48);
                ulonglong2 hB = *(const ulonglong2*)(sread + uu * 48 + 16);
                u64 w0 = wA[uu], w1 = wB[uu];
                aA0 = ffma2(w0, hA.x, aA0); aA1 = ffma2(w0, hA.y, aA1);
                aB0 = ffma2(w1, hA.x, aB0); aB1 = ffma2(w1, hA.y, aB1);
                aA2 = ffma2(w0, hB.x, aA2); aA3 = ffma2(w0, hB.y, aA3);
                aB2 = ffma2(w1, hB.x, aB2); aB3 = ffma2(w1, hB.y, aB3);
            }
            // conflict-free u64 stores: [b][col], lanes q consecutive
            *(u64*)&oA[0]            = aA0;
            *(u64*)&oA[rowl]         = aA1;
            *(u64*)&oA[2 * rowl]     = aA2;
            *(u64*)&oA[3 * rowl]     = aA3;
            *(u64*)&oA[coffs]            = aB0;
            *(u64*)&oA[rowl + coffs]     = aB1;
            *(u64*)&oA[2 * rowl + coffs] = aB2;
            *(u64*)&oA[3 * rowl + coffs] = aB3;
        }
        __syncthreads();

        // ================= Phase B: gates + gather stores =================
        if (tid < 128) {
            // GRU2 gates, step k: thread = (u=lane, c), batches 2c, 2c+1
            int u = tid & 63, c = tid >> 6;
            int r0 = (2 * c) * 192 + u, r1 = r0 + 192;
            #define PS2(PF, idx) (PF[(idx)] + PF[768 + (idx)])
            #define PS4(PF, idx) ((PF[(idx)] + PF[768 + (idx)]) + (PF[1536 + (idx)] + PF[2304 + (idx)]))
            float xz0 = PS2(P2f, r0),       xz1 = PS2(P2f, r1);
            float xr0 = PS2(P2f, r0 + 64),  xr1 = PS2(P2f, r1 + 64);
            float xh0 = PS2(P2f, r0 + 128), xh1 = PS2(P2f, r1 + 128);
            float hz0 = PS4(P3f, r0),       hz1 = PS4(P3f, r1);
            float hr0 = PS4(P3f, r0 + 64),  hr1 = PS4(P3f, r1 + 64);
            float hh0 = PS4(P3f, r0 + 128), hh1 = PS4(P3f, r1 + 128);
            float o0, o1, dummy;
            upk2(h2s[u * 6 + 2 * c], o0, dummy);
            upk2(h2s[u * 6 + 2 * c + 1], o1, dummy);
            float n0 = gru1s(xz0, hz0, xr0, hr0, xh0, hh0, o0);
            float n1 = gru1s(xz1, hz1, xr1, hr1, xh1, hh1, o1);
            h2s[u * 6 + 2 * c]     = pk2(n0, n0);
            h2s[u * 6 + 2 * c + 1] = pk2(n1, n1);
        } else if (tid < 192) {
            // GRU1 gates, step k+1
            if (k < TT - 1) {
                int t2 = tid - 128;
                int u = t2 & 31, c = t2 >> 5;
                const float* xb = xg1 + ((k + 1) & 1) * 384;
                int r0 = (2 * c) * 96 + u, r1 = r0 + 96;
                #define PS21(PF, idx) (PF[(idx)] + PF[384 + (idx)])
                float hz0 = PS21(P1f, r0),      hz1 = PS21(P1f, r1);
                float hr0 = PS21(P1f, r0 + 32), hr1 = PS21(P1f, r1 + 32);
                float hh0 = PS21(P1f, r0 + 64), hh1 = PS21(P1f, r1 + 64);
                float o0, o1, dummy;
                upk2(h1s[u * 6 + 2 * c], o0, dummy);
                upk2(h1s[u * 6 + 2 * c + 1], o1, dummy);
                float n0 = gru1s(xb[r0], hz0, xb[r0 + 32], hr0, xb[r0 + 64], hh0, o0);
                float n1 = gru1s(xb[r1], hz1, xb[r1 + 32], hr1, xb[r1 + 64], hh1, o1);
                h1s[u * 6 + 2 * c]     = pk2(n0, n0);
                h1s[u * 6 + 2 * c + 1] = pk2(n1, n1);
            }
        }
        if (gi >= 0) {
            if (k < TT - 2) {
                float* xb = xg1 + ((k + 2) & 1) * 384;
                xb[gi] = gv0;
                xb[gi + 144] = gv1;
                if (gi < 96) xb[gi + 288] = gv2;
            }
            if (((k + 3) & 31) == 0 && (k + 3) < TT && gi < 128) {
                int b = gi >> 5, o = gi & 31;
                tok[b * 32 + o] = tokens[(b0 + b) * TT + (k + 3) + o];
            }
        }
        __syncthreads();
    }

    // ================= Epilogue: GLU + dense + sigmoid =================
    float* ags = P3f;   // [4][256] alias
    float* gws = P2f;   // [4][128] alias
    if (tid < 256) {
        int c = tid;
        float bgv = bg[c];
        u64 acc0 = pk2(bgv, bgv), acc1 = acc0;
        #pragma unroll
        for (int u = 0; u < 64; u++) {
            const u64* hr = h2s + u * 6;
            float wv = __ldg(&wg[u * 256 + c]);
            u64 w = pk2(wv, wv);
            float f0, f1, f2, f3, d_;
            upk2(hr[0], f0, d_); upk2(hr[1], f1, d_);
            upk2(hr[2], f2, d_); upk2(hr[3], f3, d_);
            acc0 = ffma2(w, pk2(f0, f1), acc0);
            acc1 = ffma2(w, pk2(f2, f3), acc1);
        }
        float f0, f1;
        upk2(acc0, f0, f1); ags[0 * 256 + c] = f0; ags[1 * 256 + c] = f1;
        upk2(acc1, f0, f1); ags[2 * 256 + c] = f0; ags[3 * 256 + c] = f1;
    }
    __syncthreads();
    for (int i = tid; i < 512; i += NT) {
        int b = i >> 7, kk = i & 127;
        float g = ags[b * 256 + kk] * sgm(ags[b * 256 + 128 + kk]);
        gws[b * 128 + kk] = g * __ldg(&wd[kk]);
    }
    __syncthreads();
    if (tid < BB) {
        float s = bd[0];
        #pragma unroll
        for (int kk = 0; kk < 128; kk++) s += gws[tid * 128 + kk];
        out[b0 + tid] = sgm(s);
    }
}

// ---------------------------------------------------------------------------
extern "C" void kernel_launch(void* const* d_in, const int* in_sizes, int n_in,
                              void* d_out, int out_size) {
    (void)in_sizes; (void)n_in; (void)out_size;
    const int*   tokens = (const int*)  d_in[0];
    const float* emb    = (const float*)d_in[1];
    const float* kx1    = (const float*)d_in[2];
    const float* kh1    = (const float*)d_in[3];
    const float* b1     = (const float*)d_in[4];
    const float* kx2    = (const float*)d_in[5];
    const float* kh2    = (const float*)d_in[6];
    const float* b2     = (const float*)d_in[7];
    const float* wg     = (const float*)d_in[8];
    const float* bg     = (const float*)d_in[9];
    const float* wd     = (const float*)d_in[10];
    const float* bd     = (const float*)d_in[11];

    static int smem_set = 0;
    if (!smem_set) {
        cudaFuncSetAttribute(rnn_kernel,
                             cudaFuncAttributeMaxDynamicSharedMemorySize, SMEM_SZ);
        smem_set = 1;
    }

    proj_kernel<<<(VSZ + 15) / 16, 256>>>(emb, kx1, b1);
    rnn_kernel<<<BSZ / BB, NT, SMEM_SZ>>>(tokens, kh1, b1, kx2, kh2, b2,
                                          wg, bg, wd, bd, (float*)d_out);
}

// round 10
// speedup vs baseline: 1.2528x; 1.0407x over previous
#include <cuda_runtime.h>

#define VSZ 50257
#define Dk  50
#define TT  1024
#define BSZ 1024
#define BB  4
#define NT  336

// Precomputed emb @ kx1 + b1[0] table: [V, 96] fp32 (L2-resident, 19.3MB)
__device__ float g_proj1[VSZ * 96];

typedef unsigned long long u64;

__device__ __forceinline__ u64 pk2(float a, float b) {
    u64 r; asm("mov.b64 %0, {%1, %2};" : "=l"(r) : "f"(a), "f"(b)); return r;
}
__device__ __forceinline__ void upk2(u64 v, float& a, float& b) {
    asm("mov.b64 {%0, %1}, %2;" : "=f"(a), "=f"(b) : "l"(v));
}
__device__ __forceinline__ u64 ffma2(u64 a, u64 b, u64 c) {
    u64 d; asm("fma.rn.f32x2 %0, %1, %2, %3;" : "=l"(d) : "l"(a), "l"(b), "l"(c)); return d;
}
__device__ __forceinline__ float sgm(float x) { return 1.0f / (1.0f + __expf(-x)); }
__device__ __forceinline__ float tnh(float x) { return 2.0f * sgm(2.0f * x) - 1.0f; }

__device__ __forceinline__ float gru1s(float xz, float hz, float xr, float hr,
                                       float xh, float hh, float hold) {
    float z = sgm(xz + hz);
    float r = sgm(xr + hr);
    float c = tnh(xh + r * hh);
    return z * hold + (1.0f - z) * c;
}

// ---------------------------------------------------------------------------
__global__ void proj_kernel(const float* __restrict__ emb,
                            const float* __restrict__ kx1,
                            const float* __restrict__ b1) {
    __shared__ float kxs[Dk * 96];
    __shared__ float embs[16 * Dk];
    int tid = threadIdx.x;
    for (int i = tid; i < Dk * 96; i += 256) kxs[i] = kx1[i];
    int vbase = blockIdx.x * 16;
    for (int i = tid; i < 16 * Dk; i += 256) {
        int r = i / Dk, d = i - r * Dk;
        int v = vbase + r;
        embs[i] = (v < VSZ) ? emb[v * Dk + d] : 0.0f;
    }
    __syncthreads();
    for (int i = tid; i < 16 * 96; i += 256) {
        int r = i / 96, j = i - r * 96;
        int v = vbase + r;
        if (v >= VSZ) continue;
        float acc = b1[j];
        #pragma unroll
        for (int d = 0; d < Dk; d++)
            acc = fmaf(embs[r * Dk + d], kxs[d * 96 + j], acc);
        g_proj1[v * 96 + j] = acc;
    }
}

// ---------------------------------------------------------------------------
// Shared layout (bytes), BB=4 batches per CTA.
// States: [u][6] u64 rows (48B, 16B-aligned; entries are dup pairs (h,h),
//   slots 0..3 = batches 0..3). GEMM reads 16B broadcast; gate writes deg-4.
// P partial buffers: [buf][batch(4)][cols] f32.
//   GEMM stores: u64 at [b][2q], lanes q consecutive -> conflict-free.
//   Gate reads: [b][u], lanes u consecutive -> coalesced LDS.32.
// ---------------------------------------------------------------------------
#define OFF_H1S  0        // 32*6 u64 = 1536
#define OFF_H2S  1536     // 64*6 u64 = 3072
#define OFF_P3   4608     // 4 bufs x [4][192] f32 = 4*3072
#define OFF_P2   16896    // 2 bufs x [4][192] f32 = 2*3072
#define OFF_P1   23040    // 2 bufs x [4][96]  f32 = 2*1536
#define OFF_XG1  26112    // 2 bufs x [4][96]  f32 = 2*1536
#define OFF_TOK  29184    // [4][32] int = 512
#define SMEM_SZ  29696

__global__ void __launch_bounds__(NT, 2) rnn_kernel(
    const int*   __restrict__ tokens,
    const float* __restrict__ kh1,   // [32][96]
    const float* __restrict__ b1,    // [2][96]
    const float* __restrict__ kx2,   // [32][192]
    const float* __restrict__ kh2,   // [64][192]
    const float* __restrict__ b2,    // [2][192]
    const float* __restrict__ wg,    // [64][256]
    const float* __restrict__ bg,    // [256]
    const float* __restrict__ wd,    // [128]
    const float* __restrict__ bd,    // [1]
    float*       __restrict__ out)
{
    extern __shared__ char sbuf[];
    u64*   h1s = (u64*)(sbuf + OFF_H1S);   // [u][6]
    u64*   h2s = (u64*)(sbuf + OFF_H2S);   // [u][6]
    float* P3f = (float*)(sbuf + OFF_P3);  // bufs stride 768 floats
    float* P2f = (float*)(sbuf + OFF_P2);  // bufs stride 768 floats
    float* P1f = (float*)(sbuf + OFF_P1);  // bufs stride 384 floats
    float* xg1 = (float*)(sbuf + OFF_XG1); // bufs stride 384 floats
    int*   tok = (int*)(sbuf + OFF_TOK);

    const int tid = threadIdx.x;
    const int b0  = blockIdx.x * BB;

    // ------------- role decode + weights into registers -------------
    // G3 (hm2=h2@kh2): tid [0,192):   uh=tid/48 (4 x 16u), q=tid%48
    // G2 (xg2=h1@kx2): tid [192,288): uh=t/48 (2 x 16u),   q=t%48
    // G1 (hm1=h1@kh1): tid [288,336): uh=t/24 (2 x 16u),   q=t%24
    u64 wA[16], wB[16];
    u64 bqA = 0ull, bqB = 0ull;
    const char* sread;
    float* oA;
    int coffs;
    {
        const float* wsrc; const float* bsrc; const char* stateb; float* pbase;
        int uh, q, ncols;
        if (tid < 192) {
            uh = tid / 48; q = tid % 48;
            wsrc = kh2; bsrc = b2 + 192; stateb = sbuf + OFF_H2S;
            ncols = 192; coffs = 96; pbase = P3f + uh * 768;
        } else if (tid < 288) {
            int t = tid - 192;
            uh = t / 48; q = t % 48;
            wsrc = kx2; bsrc = b2; stateb = sbuf + OFF_H1S;
            ncols = 192; coffs = 96; pbase = P2f + uh * 768;
        } else {
            int t = tid - 288;
            uh = t / 24; q = t % 24;
            wsrc = kh1; bsrc = b1 + 96; stateb = sbuf + OFF_H1S;
            ncols = 96; coffs = 48; pbase = P1f + uh * 384;
        }
        int u0 = uh * 16;
        #pragma unroll
        for (int uu = 0; uu < 16; uu++) {
            float2 a = *(const float2*)&wsrc[(u0 + uu) * ncols + 2 * q];
            float2 b = *(const float2*)&wsrc[(u0 + uu) * ncols + 2 * q + coffs];
            wA[uu] = pk2(a.x, a.y); wB[uu] = pk2(b.x, b.y);
        }
        if (uh == 0) {
            float2 a = *(const float2*)&bsrc[2 * q];
            float2 b = *(const float2*)&bsrc[2 * q + coffs];
            bqA = pk2(a.x, a.y); bqB = pk2(b.x, b.y);
        }
        sread = stateb + u0 * 48;           // 16B-aligned (48 % 16 == 0)
        oA = pbase + 2 * q;
    }
    const int rowl = (tid < 288) ? 192 : 96;

    // gather mapping (tid in [192,336): 144 threads cover 384 gathers)
    const int gi = tid - 192;
    int gb0 = 0, gj0 = 0, gb1 = 0, gj1 = 0;
    if (gi >= 0) {
        gb0 = gi / 96;          gj0 = gi % 96;
        gb1 = (gi + 144) / 96;  gj1 = (gi + 144) % 96;
        // third gather (gi < 96): batch 3, col gi
    }

    // ------------- init: zero states, token chunk 0 -------------
    for (int i = tid; i < 576; i += NT) ((u64*)sbuf)[i] = 0ull;  // h1s + h2s
    if (gi >= 0 && gi < 128) {
        int b = gi >> 5, o = gi & 31;
        tok[b * 32 + o] = tokens[(b0 + b) * TT + o];
    }
    __syncthreads();
    // prefill xg1 for t=0 (buf0), t=1 (buf1); layout [b][96] linear
    for (int i = tid; i < 384; i += NT) {
        int b = i / 96, j = i - 96 * (i / 96);
        xg1[i]       = __ldg(&g_proj1[tok[b * 32 + 0] * 96 + j]);
        xg1[384 + i] = __ldg(&g_proj1[tok[b * 32 + 1] * 96 + j]);
    }
    __syncthreads();
    // GRU1 step 0 (h=0 -> recurrent term = bias)
    if (tid < 64) {
        int u = tid & 31, c = tid >> 5;
        int r0 = (2 * c) * 96 + u, r1 = r0 + 96;
        float bz = b1[96 + u], br = b1[128 + u], bhv = b1[160 + u];
        float n0 = gru1s(xg1[r0], bz, xg1[r0 + 32], br, xg1[r0 + 64], bhv, 0.0f);
        float n1 = gru1s(xg1[r1], bz, xg1[r1 + 32], br, xg1[r1 + 64], bhv, 0.0f);
        h1s[u * 6 + 2 * c]     = pk2(n0, n0);
        h1s[u * 6 + 2 * c + 1] = pk2(n1, n1);
    }
    __syncthreads();

    float gv0 = 0.0f, gv1 = 0.0f, gv2 = 0.0f;

    #pragma unroll 2
    for (int k = 0; k < TT; k++) {
        // ================= Phase A: gathers + 3 GEMMs =================
        if (gi >= 0 && k < TT - 2) {
            int slot = (k + 2) & 31;
            gv0 = __ldg(&g_proj1[tok[gb0 * 32 + slot] * 96 + gj0]);
            gv1 = __ldg(&g_proj1[tok[gb1 * 32 + slot] * 96 + gj1]);
            if (gi < 96)
                gv2 = __ldg(&g_proj1[tok[3 * 32 + slot] * 96 + gi]);
        }
        {
            u64 aA0 = bqA, aA1 = bqA, aA2 = bqA, aA3 = bqA;
            u64 aB0 = bqB, aB1 = bqB, aB2 = bqB, aB3 = bqB;
            #pragma unroll
            for (int uu = 0; uu < 16; uu++) {
                // batches 0..3, dup u64 each; 48B row stride (16B-aligned)
                ulonglong2 hA = *(const ulonglong2*)(sread + uu * 48);
                ulonglong2 hB = *(const ulonglong2*)(sread + uu * 48 + 16);
                u64 w0 = wA[uu], w1 = wB[uu];
                aA0 = ffma2(w0, hA.x, aA0); aA1 = ffma2(w0, hA.y, aA1);
                aB0 = ffma2(w1, hA.x, aB0); aB1 = ffma2(w1, hA.y, aB1);
                aA2 = ffma2(w0, hB.x, aA2); aA3 = ffma2(w0, hB.y, aA3);
                aB2 = ffma2(w1, hB.x, aB2); aB3 = ffma2(w1, hB.y, aB3);
            }
            // conflict-free u64 stores: [b][col], lanes q consecutive
            *(u64*)&oA[0]            = aA0;
            *(u64*)&oA[rowl]         = aA1;
            *(u64*)&oA[2 * rowl]     = aA2;
            *(u64*)&oA[3 * rowl]     = aA3;
            *(u64*)&oA[coffs]            = aB0;
            *(u64*)&oA[rowl + coffs]     = aB1;
            *(u64*)&oA[2 * rowl + coffs] = aB2;
            *(u64*)&oA[3 * rowl + coffs] = aB3;
        }
        __syncthreads();

        // ================= Phase B: gates + gather stores =================
        if (tid < 256) {
            // GRU2 gates, step k: thread = (u=lane, b): ONE batch each
            int u = tid & 63, b = tid >> 6;
            int r = b * 192 + u;
            #define PS2(PF, idx) (PF[(idx)] + PF[768 + (idx)])
            #define PS4(PF, idx) ((PF[(idx)] + PF[768 + (idx)]) + (PF[1536 + (idx)] + PF[2304 + (idx)]))
            float xz = PS2(P2f, r);
            float xr = PS2(P2f, r + 64);
            float xh = PS2(P2f, r + 128);
            float hz = PS4(P3f, r);
            float hr = PS4(P3f, r + 64);
            float hh = PS4(P3f, r + 128);
            float o, dmy;
            upk2(h2s[u * 6 + b], o, dmy);
            float n = gru1s(xz, hz, xr, hr, xh, hh, o);
            h2s[u * 6 + b] = pk2(n, n);
        } else if (tid < 320) {
            // GRU1 gates, step k+1 (2 batches, packed STS.128 state write)
            if (k < TT - 1) {
                int t2 = tid - 256;
                int u = t2 & 31, c = t2 >> 5;
                const float* xb = xg1 + ((k + 1) & 1) * 384;
                int r0 = (2 * c) * 96 + u, r1 = r0 + 96;
                #define PS21(PF, idx) (PF[(idx)] + PF[384 + (idx)])
                float hz0 = PS21(P1f, r0),      hz1 = PS21(P1f, r1);
                float hr0 = PS21(P1f, r0 + 32), hr1 = PS21(P1f, r1 + 32);
                float hh0 = PS21(P1f, r0 + 64), hh1 = PS21(P1f, r1 + 64);
                float o0, o1, dmy;
                upk2(h1s[u * 6 + 2 * c], o0, dmy);
                upk2(h1s[u * 6 + 2 * c + 1], o1, dmy);
                float n0 = gru1s(xb[r0], hz0, xb[r0 + 32], hr0, xb[r0 + 64], hh0, o0);
                float n1 = gru1s(xb[r1], hz1, xb[r1 + 32], hr1, xb[r1 + 64], hh1, o1);
                *(ulonglong2*)&h1s[u * 6 + 2 * c] =
                    make_ulonglong2(pk2(n0, n0), pk2(n1, n1));
            }
        }
        if (gi >= 0) {
            if (k < TT - 2) {
                float* xb = xg1 + ((k + 2) & 1) * 384;
                xb[gi] = gv0;
                xb[gi + 144] = gv1;
                if (gi < 96) xb[gi + 288] = gv2;
            }
            if (((k + 3) & 31) == 0 && (k + 3) < TT && gi < 128) {
                int b = gi >> 5, o = gi & 31;
                tok[b * 32 + o] = tokens[(b0 + b) * TT + (k + 3) + o];
            }
        }
        __syncthreads();
    }

    // ================= Epilogue: GLU + dense + sigmoid =================
    float* ags = P3f;   // [4][256] alias
    float* gws = P2f;   // [4][128] alias
    if (tid < 256) {
        int c = tid;
        float bgv = bg[c];
        u64 acc0 = pk2(bgv, bgv), acc1 = acc0;
        #pragma unroll
        for (int u = 0; u < 64; u++) {
            const u64* hr = h2s + u * 6;
            float wv = __ldg(&wg[u * 256 + c]);
            u64 w = pk2(wv, wv);
            float f0, f1, f2, f3, d_;
            upk2(hr[0], f0, d_); upk2(hr[1], f1, d_);
            upk2(hr[2], f2, d_); upk2(hr[3], f3, d_);
            acc0 = ffma2(w, pk2(f0, f1), acc0);
            acc1 = ffma2(w, pk2(f2, f3), acc1);
        }
        float f0, f1;
        upk2(acc0, f0, f1); ags[0 * 256 + c] = f0; ags[1 * 256 + c] = f1;
        upk2(acc1, f0, f1); ags[2 * 256 + c] = f0; ags[3 * 256 + c] = f1;
    }
    __syncthreads();
    for (int i = tid; i < 512; i += NT) {
        int b = i >> 7, kk = i & 127;
        float g = ags[b * 256 + kk] * sgm(ags[b * 256 + 128 + kk]);
        gws[b * 128 + kk] = g * __ldg(&wd[kk]);
    }
    __syncthreads();
    if (tid < BB) {
        float s = bd[0];
        #pragma unroll
        for (int kk = 0; kk < 128; kk++) s += gws[tid * 128 + kk];
        out[b0 + tid] = sgm(s);
    }
}

// ---------------------------------------------------------------------------
extern "C" void kernel_launch(void* const* d_in, const int* in_sizes, int n_in,
                              void* d_out, int out_size) {
    (void)in_sizes; (void)n_in; (void)out_size;
    const int*   tokens = (const int*)  d_in[0];
    const float* emb    = (const float*)d_in[1];
    const float* kx1    = (const float*)d_in[2];
    const float* kh1    = (const float*)d_in[3];
    const float* b1     = (const float*)d_in[4];
    const float* kx2    = (const float*)d_in[5];
    const float* kh2    = (const float*)d_in[6];
    const float* b2     = (const float*)d_in[7];
    const float* wg     = (const float*)d_in[8];
    const float* bg     = (const float*)d_in[9];
    const float* wd     = (const float*)d_in[10];
    const float* bd     = (const float*)d_in[11];

    static int smem_set = 0;
    if (!smem_set) {
        cudaFuncSetAttribute(rnn_kernel,
                             cudaFuncAttributeMaxDynamicSharedMemorySize, SMEM_SZ);
        smem_set = 1;
    }

    proj_kernel<<<(VSZ + 15) / 16, 256>>>(emb, kx1, b1);
    rnn_kernel<<<BSZ / BB, NT, SMEM_SZ>>>(tokens, kh1, b1, kx2, kh2, b2,
                                          wg, bg, wd, bd, (float*)d_out);
}